// round 4
// baseline (speedup 1.0000x reference)
#include <cuda_runtime.h>
#include <cstdint>

#define NUM_LEVELS 16
#define LOG2_T 19
#define TABLE_SIZE (1u << LOG2_T)
#define TABLE_MASK (TABLE_SIZE - 1u)
#define P1 2654435761u
#define P2 805459861u

// One thread per (point, level).
// x-axis hash prime is 1 -> for even ix the corner pair (ix, ix+1) maps to
// aligned consecutive table slots {2m, 2m+1}: one float4 load fetches both.
// Even-ix lanes: 4 LDG.128. Odd-ix lanes: 4 LDG.128 + 4 predicated LDG.64.
// Avg 6 gather-wavefronts/thread = the floor for this hash structure.
// This round: squeeze regs (launch_bounds minBlocks=7) to restore occupancy
// and saturate the L1tex wavefront pipe.
__global__ __launch_bounds__(256, 7) void hashenc_kernel(
    const float* __restrict__ x,
    const float* __restrict__ tables,
    float* __restrict__ out,
    int N)
{
    int gid = blockIdx.x * blockDim.x + threadIdx.x;
    if (gid >= N * NUM_LEVELS) return;
    int p = gid >> 4;          // point index
    int l = gid & 15;          // level index

    float x0 = x[p * 3 + 0];
    float x1 = x[p * 3 + 1];
    float x2 = x[p * 3 + 2];

    const float hi = 1.0f - 1e-6f;
    x0 = fminf(fmaxf((x0 + 1.0f) * 0.5f, 0.0f), hi);
    x1 = fminf(fmaxf((x1 + 1.0f) * 0.5f, 0.0f), hi);
    x2 = fminf(fmaxf((x2 + 1.0f) * 0.5f, 0.0f), hi);

    float res = (float)(16 << l);
    float s0 = x0 * res, s1 = x1 * res, s2 = x2 * res;
    float f0 = floorf(s0), f1 = floorf(s1), f2 = floorf(s2);
    float fx = s0 - f0, fy = s1 - f1, fz = s2 - f2;
    uint32_t ix = (uint32_t)(int)f0;
    uint32_t iy = (uint32_t)(int)f1;
    uint32_t iz = (uint32_t)(int)f2;

    uint32_t ay0 = iy * P1, ay1 = (iy + 1u) * P1;
    uint32_t az0 = iz * P2, az1 = (iz + 1u) * P2;
    uint32_t lv = (uint32_t)l;

    // Per-(y,z)-combo hash keys. c: 0=(y0,z0) 1=(y0,z1) 2=(y1,z0) 3=(y1,z1)
    uint32_t K0 = ay0 ^ az0 ^ lv;
    uint32_t K1 = K0 ^ az0 ^ az1;      // ay0 ^ az1 ^ lv
    uint32_t K2 = K0 ^ ay0 ^ ay1;      // ay1 ^ az0 ^ lv
    uint32_t K3 = K2 ^ az0 ^ az1;      // ay1 ^ az1 ^ lv

    const float2* __restrict__ tbl  = (const float2*)tables + (size_t)l * TABLE_SIZE;
    const float4* __restrict__ tbl4 = (const float4*)tbl;

    bool odd = (ix & 1u) != 0u;
    uint32_t ix1 = ix + 1u;

    // Pack the 4 "idx0 is upper half" bits into one mask register so the
    // full idx values need not stay live across the loads.
    uint32_t i00 = (ix ^ K0) & TABLE_MASK;
    uint32_t i01 = (ix ^ K1) & TABLE_MASK;
    uint32_t i02 = (ix ^ K2) & TABLE_MASK;
    uint32_t i03 = (ix ^ K3) & TABLE_MASK;
    uint32_t selmask = (i00 & 1u) | ((i01 & 1u) << 1) | ((i02 & 1u) << 2) | ((i03 & 1u) << 3);

    // 4 paired loads (issue all up front for MLP)
    float4 q0 = __ldg(&tbl4[i00 >> 1]);
    float4 q1 = __ldg(&tbl4[i01 >> 1]);
    float4 q2 = __ldg(&tbl4[i02 >> 1]);
    float4 q3 = __ldg(&tbl4[i03 >> 1]);

    // Odd-ix lanes: 4 extra predicated 8B gathers for the (ix+1) corners.
    float2 eo0, eo1, eo2, eo3;
    if (odd) {
        eo0 = __ldg(&tbl[(ix1 ^ K0) & TABLE_MASK]);
        eo1 = __ldg(&tbl[(ix1 ^ K1) & TABLE_MASK]);
        eo2 = __ldg(&tbl[(ix1 ^ K2) & TABLE_MASK]);
        eo3 = __ldg(&tbl[(ix1 ^ K3) & TABLE_MASK]);
    } else {
        eo0 = eo1 = eo2 = eo3 = make_float2(0.0f, 0.0f);
    }

    float gx = 1.0f - fx, gy = 1.0f - fy, gz = 1.0f - fz;
    float w0 = gy * gz;
    float w1 = gy * fz;
    float w2 = fy * gz;
    float w3 = fy * fz;

    float o0 = 0.0f, o1 = 0.0f;
#define COMBINE(Q, EO, BIT, W)                                   \
    {                                                            \
        bool sel = (selmask >> BIT) & 1u;                        \
        float e0x = sel ? Q.z : Q.x;                             \
        float e0y = sel ? Q.w : Q.y;                             \
        float epx = sel ? Q.x : Q.z;                             \
        float epy = sel ? Q.y : Q.w;                             \
        float e4x = odd ? EO.x : epx;                            \
        float e4y = odd ? EO.y : epy;                            \
        o0 += (e0x * gx + e4x * fx) * W;                         \
        o1 += (e0y * gx + e4y * fx) * W;                         \
    }
    COMBINE(q0, eo0, 0, w0)
    COMBINE(q1, eo1, 1, w1)
    COMBINE(q2, eo2, 2, w2)
    COMBINE(q3, eo3, 3, w3)
#undef COMBINE

    // out[p, l*2 + {0,1}]; consecutive threads -> contiguous 8B stores.
    float2* orow = (float2*)(out + (size_t)p * (NUM_LEVELS * 2));
    orow[l] = make_float2(o0, o1);
}

extern "C" void kernel_launch(void* const* d_in, const int* in_sizes, int n_in,
                              void* d_out, int out_size) {
    const float* x      = (const float*)d_in[0];
    const float* tables = (const float*)d_in[1];
    float* out          = (float*)d_out;
    int N = in_sizes[0] / 3;

    int total = N * NUM_LEVELS;
    int threads = 256;
    int blocks = (total + threads - 1) / threads;
    hashenc_kernel<<<blocks, threads>>>(x, tables, out, N);
}

// round 5
// speedup vs baseline: 1.4147x; 1.4147x over previous
#include <cuda_runtime.h>
#include <cstdint>

#define NUM_LEVELS 16
#define LOG2_T 19
#define TABLE_SIZE (1u << LOG2_T)
#define TABLE_MASK (TABLE_SIZE - 1u)
#define P1 2654435761u
#define P2 805459861u

// TWO threads per (point, level) item: thread-half h handles the y=iy+h pair
// of yz-combos (2 float4 paired loads + 2 predicated odd-ix float2 loads).
// x-axis hash prime is 1 -> even ix corner pair {ix, ix+1} = aligned table
// slots {2m, 2m+1}: one float4 fetches both corners.
// Gather wavefronts/item unchanged (the floor: avg 6), but per-thread register
// state halves -> high occupancy WITHOUT forcing regs (R4 spill lesson).
__global__ __launch_bounds__(256) void hashenc_kernel(
    const float* __restrict__ x,
    const float* __restrict__ tables,
    float* __restrict__ out,
    int N)
{
    int t = blockIdx.x * blockDim.x + threadIdx.x;
    int item = t >> 1;
    int half = t & 1;
    if (item >= N * NUM_LEVELS) return;
    int p = item >> 4;          // point index
    int l = item & 15;          // level index

    // 32 consecutive threads cover one point (16 levels x 2 halves) -> broadcast
    float x0 = x[p * 3 + 0];
    float x1 = x[p * 3 + 1];
    float x2 = x[p * 3 + 2];

    const float hi = 1.0f - 1e-6f;
    x0 = fminf(fmaxf((x0 + 1.0f) * 0.5f, 0.0f), hi);
    x1 = fminf(fmaxf((x1 + 1.0f) * 0.5f, 0.0f), hi);
    x2 = fminf(fmaxf((x2 + 1.0f) * 0.5f, 0.0f), hi);

    float res = (float)(16 << l);
    float s0 = x0 * res, s1 = x1 * res, s2 = x2 * res;
    float f0 = floorf(s0), f1 = floorf(s1), f2 = floorf(s2);
    float fx = s0 - f0, fy = s1 - f1, fz = s2 - f2;
    uint32_t ix = (uint32_t)(int)f0;
    uint32_t iy = (uint32_t)(int)f1;
    uint32_t iz = (uint32_t)(int)f2;

    // this thread's y coordinate: iy + half
    uint32_t ay = (iy + (uint32_t)half) * P1;
    uint32_t K0 = ay ^ (iz * P2) ^ (uint32_t)l;          // (y, z0)
    uint32_t K1 = ay ^ ((iz + 1u) * P2) ^ (uint32_t)l;   // (y, z1)

    const float2* __restrict__ tbl  = (const float2*)tables + (size_t)l * TABLE_SIZE;
    const float4* __restrict__ tbl4 = (const float4*)tbl;

    bool odd = (ix & 1u) != 0u;
    uint32_t ix1 = ix + 1u;

    uint32_t i00 = (ix ^ K0) & TABLE_MASK;
    uint32_t i01 = (ix ^ K1) & TABLE_MASK;

    // paired loads: float4 covering the aligned slot-pair containing idx0
    float4 q0 = __ldg(&tbl4[i00 >> 1]);
    float4 q1 = __ldg(&tbl4[i01 >> 1]);

    // odd-ix lanes: (ix+1) corner not adjacent -> 2 predicated 8B gathers
    float2 eo0, eo1;
    if (odd) {
        eo0 = __ldg(&tbl[(ix1 ^ K0) & TABLE_MASK]);
        eo1 = __ldg(&tbl[(ix1 ^ K1) & TABLE_MASK]);
    } else {
        eo0 = eo1 = make_float2(0.0f, 0.0f);
    }

    float gx = 1.0f - fx, gz = 1.0f - fz;
    float wy = half ? fy : (1.0f - fy);
    float wA = wy * gz;      // (y, z0)
    float wB = wy * fz;      // (y, z1)

    float o0 = 0.0f, o1 = 0.0f;
#define COMBINE(Q, EO, I0, W)                                    \
    {                                                            \
        bool sel = (I0 & 1u) != 0u;                              \
        float e0x = sel ? Q.z : Q.x;                             \
        float e0y = sel ? Q.w : Q.y;                             \
        float epx = sel ? Q.x : Q.z;                             \
        float epy = sel ? Q.y : Q.w;                             \
        float e4x = odd ? EO.x : epx;                            \
        float e4y = odd ? EO.y : epy;                            \
        o0 += (e0x * gx + e4x * fx) * W;                         \
        o1 += (e0y * gx + e4y * fx) * W;                         \
    }
    COMBINE(q0, eo0, i00, wA)
    COMBINE(q1, eo1, i01, wB)
#undef COMBINE

    // pair reduction: lanes (2k, 2k+1) hold the two y-halves of one item
    o0 += __shfl_xor_sync(0xFFFFFFFFu, o0, 1);
    o1 += __shfl_xor_sync(0xFFFFFFFFu, o1, 1);

    if (half == 0) {
        float2* orow = (float2*)(out + (size_t)p * (NUM_LEVELS * 2));
        orow[l] = make_float2(o0, o1);
    }
}

extern "C" void kernel_launch(void* const* d_in, const int* in_sizes, int n_in,
                              void* d_out, int out_size) {
    const float* x      = (const float*)d_in[0];
    const float* tables = (const float*)d_in[1];
    float* out          = (float*)d_out;
    int N = in_sizes[0] / 3;

    long long total = (long long)N * NUM_LEVELS * 2;
    int threads = 256;
    int blocks = (int)((total + threads - 1) / threads);
    hashenc_kernel<<<blocks, threads>>>(x, tables, out, N);
}